// round 1
// baseline (speedup 1.0000x reference)
#include <cuda_runtime.h>

// CuGraphSAGEConv fused kernel:
//   agg[j]  = mean_{e in [colptr[j], colptr[j+1])} x[row[e]]
//   out[j]  = concat(agg[j], x[j]) @ W^T + b
//
// One block = 64 nodes. Phase 1: warp-per-node aggregation into k-major
// shared featT[128][68]. Phase 2: register-tiled (4x4) FFMA2 mini-GEMM
// against Wt[128][68] (W transposed in shared).

#define D_IN    64
#define DK      128   // 2*D_IN
#define D_OUT   64
#define NPB     64    // nodes per block
#define THREADS 256
#define LDF     68    // padded leading dim (16B aligned, conflict-free reads)

static const int SMEM_BYTES = 2 * DK * LDF * (int)sizeof(float);  // 69632

// ---- packed f32x2 helpers (Blackwell) ----
__device__ __forceinline__ unsigned long long pk2dup(float a) {
    unsigned long long d;
    asm("mov.b64 %0, {%1,%1};" : "=l"(d) : "f"(a));
    return d;
}
__device__ __forceinline__ void fma2(unsigned long long& c,
                                     unsigned long long a,
                                     unsigned long long b) {
    asm("fma.rn.f32x2 %0, %1, %2, %0;" : "+l"(c) : "l"(a), "l"(b));
}
__device__ __forceinline__ float2 upk2(unsigned long long d) {
    float2 r;
    asm("mov.b64 {%0,%1}, %2;" : "=f"(r.x), "=f"(r.y) : "l"(d));
    return r;
}

extern __shared__ float smem[];

__global__ __launch_bounds__(THREADS)
void sage_fused_kernel(const float* __restrict__ x,
                       const int*   __restrict__ row,
                       const int*   __restrict__ colptr,
                       const float* __restrict__ W,
                       const float* __restrict__ b,
                       float*       __restrict__ out,
                       int N)
{
    float* featT = smem;               // [DK][LDF]  k-major features
    float* Wt    = smem + DK * LDF;    // [DK][LDF]  W transposed (k-major)

    const int tid  = threadIdx.x;
    const int warp = tid >> 5;
    const int lane = tid & 31;
    const int base = blockIdx.x * NPB;

    // ---- load W transposed into shared: Wt[k][o] = W[o*128 + k] ----
    #pragma unroll
    for (int i = tid; i < D_OUT * DK; i += THREADS) {
        int o = i >> 7;       // / 128
        int k = i & 127;
        Wt[k * LDF + o] = W[i];
    }

    // ---- Phase 1: aggregation, warp handles 8 consecutive nodes ----
    const float2* __restrict__ xp = reinterpret_cast<const float2*>(x);
    #pragma unroll 1
    for (int i = 0; i < NPB / 8; i++) {
        const int nl   = warp * 8 + i;
        const int node = base + nl;
        float2 acc = make_float2(0.f, 0.f);
        float2 xr  = make_float2(0.f, 0.f);
        if (node < N) {
            const int e0 = __ldg(colptr + node);
            const int e1 = __ldg(colptr + node + 1);
            int e = e0;
            // 4-way unroll for memory-level parallelism against L2 latency
            for (; e + 4 <= e1; e += 4) {
                int s0 = __ldg(row + e);
                int s1 = __ldg(row + e + 1);
                int s2 = __ldg(row + e + 2);
                int s3 = __ldg(row + e + 3);
                float2 v0 = __ldg(xp + s0 * 32 + lane);
                float2 v1 = __ldg(xp + s1 * 32 + lane);
                float2 v2 = __ldg(xp + s2 * 32 + lane);
                float2 v3 = __ldg(xp + s3 * 32 + lane);
                acc.x += (v0.x + v1.x) + (v2.x + v3.x);
                acc.y += (v0.y + v1.y) + (v2.y + v3.y);
            }
            for (; e < e1; e++) {
                int s = __ldg(row + e);
                float2 v = __ldg(xp + s * 32 + lane);
                acc.x += v.x;
                acc.y += v.y;
            }
            int deg = e1 - e0;
            float inv = 1.f / (float)(deg > 0 ? deg : 1);
            acc.x *= inv;
            acc.y *= inv;
            xr = __ldg(xp + node * 32 + lane);
        }
        // k-major store (pad 68 -> mild 8-way write conflict, negligible)
        featT[(2 * lane)            * LDF + nl] = acc.x;
        featT[(2 * lane + 1)        * LDF + nl] = acc.y;
        featT[(D_IN + 2 * lane)     * LDF + nl] = xr.x;
        featT[(D_IN + 2 * lane + 1) * LDF + nl] = xr.y;
    }
    __syncthreads();

    // ---- Phase 2: mini-GEMM  C[64 nodes][64 outs] = featT^T @ Wt ----
    // thread (ty, tx): 4 nodes x 4 outputs register tile
    const int tx = tid & 15;
    const int ty = tid >> 4;

    unsigned long long c[4][2];
    #pragma unroll
    for (int r = 0; r < 4; r++) { c[r][0] = 0ull; c[r][1] = 0ull; }

    const float* fa = featT + 4 * ty;   // 16B aligned (LDF*4 = 272 = 16*17)
    const float* wb = Wt    + 4 * tx;

    #pragma unroll 8
    for (int k = 0; k < DK; k++) {
        float4 a4 = *reinterpret_cast<const float4*>(fa + k * LDF);
        ulonglong2 b2 = *reinterpret_cast<const ulonglong2*>(wb + k * LDF);
        #pragma unroll
        for (int r = 0; r < 4; r++) {
            float ar = (r == 0) ? a4.x : (r == 1) ? a4.y : (r == 2) ? a4.z : a4.w;
            unsigned long long ad = pk2dup(ar);
            fma2(c[r][0], ad, b2.x);
            fma2(c[r][1], ad, b2.y);
        }
    }

    float4 bb = *reinterpret_cast<const float4*>(b + 4 * tx);
    #pragma unroll
    for (int r = 0; r < 4; r++) {
        int node = base + 4 * ty + r;
        if (node < N) {
            float2 p0 = upk2(c[r][0]);
            float2 p1 = upk2(c[r][1]);
            float4 o4 = make_float4(p0.x + bb.x, p0.y + bb.y,
                                    p1.x + bb.z, p1.y + bb.w);
            *reinterpret_cast<float4*>(out + (size_t)node * D_OUT + 4 * tx) = o4;
        }
    }
}

extern "C" void kernel_launch(void* const* d_in, const int* in_sizes, int n_in,
                              void* d_out, int out_size)
{
    const float* x      = (const float*)d_in[0];
    const int*   row    = (const int*)  d_in[1];
    const int*   colptr = (const int*)  d_in[2];
    const float* W      = (const float*)d_in[3];
    const float* b      = (const float*)d_in[4];
    float*       out    = (float*)d_out;

    const int N = in_sizes[2] - 1;   // 100000

    static bool attr_set = false;
    // (idempotent host-side attribute set; not a stream op, capture-safe)
    cudaFuncSetAttribute(sage_fused_kernel,
                         cudaFuncAttributeMaxDynamicSharedMemorySize,
                         SMEM_BYTES);
    (void)attr_set;

    int grid = (N + NPB - 1) / NPB;
    sage_fused_kernel<<<grid, THREADS, SMEM_BYTES>>>(x, row, colptr, W, b, out, N);
}

// round 2
// speedup vs baseline: 1.0626x; 1.0626x over previous
#include <cuda_runtime.h>

// CuGraphSAGEConv fused:
//   agg[j] = mean_{e in [colptr[j],colptr[j+1])} x[row[e]]
//   out[j] = concat(agg[j], x[j]) @ W^T + b
//
// Block = 64 nodes, 512 threads.
// Phase 1: 16-lane group per node (float4 over 64 dims), 2 nodes per warp
//          concurrently, 4-edge unroll -> 8 independent load chains/warp.
//          Results stored NODE-MAJOR in shared (no transpose).
// Phase 2: f32x2 GEMM packed along k: acc2 += (a_k,a_k1)*(W_ok,W_ok1),
//          horizontal add at the end. No dup-MOVs, no transposes.

#define THREADS 512
#define NPB     64
#define LDW     66          // float4 leading dim for staged W rows
#define NKQ     32          // 128 k / 4

static const int SMEM_BYTES = (NPB * 32 + NKQ * LDW) * 16;  // 66560 B

__device__ __forceinline__ void fma2(unsigned long long& c,
                                     unsigned long long a,
                                     unsigned long long b) {
    asm("fma.rn.f32x2 %0, %1, %2, %0;" : "+l"(c) : "l"(a), "l"(b));
}
__device__ __forceinline__ float2 upk2(unsigned long long d) {
    float2 r;
    asm("mov.b64 {%0,%1}, %2;" : "=f"(r.x), "=f"(r.y) : "l"(d));
    return r;
}

extern __shared__ float4 smem4[];

__global__ __launch_bounds__(THREADS, 2)
void sage_fused_kernel(const float* __restrict__ x,
                       const int*   __restrict__ row,
                       const int*   __restrict__ colptr,
                       const float* __restrict__ W,
                       const float* __restrict__ b,
                       float*       __restrict__ out,
                       int N)
{
    float4* featq = smem4;            // [NPB][32] float4, node-major feature rows
    float4* Wsq   = smem4 + NPB * 32; // [NKQ][LDW] float4: Wsq[kq][o] = W[o][4kq..4kq+3]

    const int tid  = threadIdx.x;
    const int base = blockIdx.x * NPB;

    // ---- stage W into shared as [kq][o] float4 tiles ----
    const float4* Wg = reinterpret_cast<const float4*>(W);  // [64 o][32 kq]
    #pragma unroll
    for (int t = 0; t < 4; t++) {
        int idx = tid + t * THREADS;       // 0..2047
        int o   = idx >> 5;
        int kq  = idx & 31;
        Wsq[kq * LDW + o] = Wg[idx];       // coalesced global read per warp
    }

    // ---- Phase 1: aggregation, 16-lane group per node ----
    const int warp = tid >> 5;
    const int lane = tid & 31;
    const int g    = lane >> 4;     // group 0/1 within warp
    const int gl   = lane & 15;     // lane within group -> float4 index in row
    const float4* x4 = reinterpret_cast<const float4*>(x);

    #pragma unroll
    for (int i = 0; i < 2; i++) {
        const int nl   = warp * 4 + i * 2 + g;   // local node 0..63
        const int node = base + nl;
        float4 acc = make_float4(0.f, 0.f, 0.f, 0.f);
        float4 xr  = make_float4(0.f, 0.f, 0.f, 0.f);
        if (node < N) {
            const int e0 = __ldg(colptr + node);
            const int e1 = __ldg(colptr + node + 1);
            int e = e0;
            for (; e + 4 <= e1; e += 4) {
                int s0 = __ldg(row + e);
                int s1 = __ldg(row + e + 1);
                int s2 = __ldg(row + e + 2);
                int s3 = __ldg(row + e + 3);
                float4 v0 = __ldg(x4 + s0 * 16 + gl);
                float4 v1 = __ldg(x4 + s1 * 16 + gl);
                float4 v2 = __ldg(x4 + s2 * 16 + gl);
                float4 v3 = __ldg(x4 + s3 * 16 + gl);
                acc.x += (v0.x + v1.x) + (v2.x + v3.x);
                acc.y += (v0.y + v1.y) + (v2.y + v3.y);
                acc.z += (v0.z + v1.z) + (v2.z + v3.z);
                acc.w += (v0.w + v1.w) + (v2.w + v3.w);
            }
            for (; e < e1; e++) {
                int s = __ldg(row + e);
                float4 v = __ldg(x4 + s * 16 + gl);
                acc.x += v.x; acc.y += v.y; acc.z += v.z; acc.w += v.w;
            }
            int deg = e1 - e0;
            float inv = 1.f / (float)(deg > 0 ? deg : 1);
            acc.x *= inv; acc.y *= inv; acc.z *= inv; acc.w *= inv;
            xr = __ldg(x4 + node * 16 + gl);
        }
        featq[nl * 32 + gl]      = acc;   // agg half  (k 0..63)
        featq[nl * 32 + 16 + gl] = xr;    // root half (k 64..127)
    }
    __syncthreads();

    // ---- Phase 2: C[64 nodes][64 outs] = feat @ W^T, f32x2 k-pairs ----
    // thread: 2 nodes (2*ty, 2*ty+1) x 4 outs (tx + 16j)
    const int tx = tid & 15;
    const int ty = tid >> 4;     // 0..31

    const ulonglong2* fA = reinterpret_cast<const ulonglong2*>(featq);
    const ulonglong2* wA = reinterpret_cast<const ulonglong2*>(Wsq);
    const ulonglong2* a0p = fA + (2 * ty)     * 32;
    const ulonglong2* a1p = fA + (2 * ty + 1) * 32;
    const ulonglong2* wp  = wA + tx;

    unsigned long long acc[2][4];
    #pragma unroll
    for (int r = 0; r < 2; r++)
        #pragma unroll
        for (int j = 0; j < 4; j++) acc[r][j] = 0ull;

    #pragma unroll 2
    for (int kq = 0; kq < NKQ; kq++) {
        ulonglong2 A0 = a0p[kq];
        ulonglong2 A1 = a1p[kq];
        const ulonglong2* w = wp + kq * LDW;
        ulonglong2 B0 = w[0];
        ulonglong2 B1 = w[16];
        ulonglong2 B2 = w[32];
        ulonglong2 B3 = w[48];
        fma2(acc[0][0], A0.x, B0.x); fma2(acc[0][0], A0.y, B0.y);
        fma2(acc[0][1], A0.x, B1.x); fma2(acc[0][1], A0.y, B1.y);
        fma2(acc[0][2], A0.x, B2.x); fma2(acc[0][2], A0.y, B2.y);
        fma2(acc[0][3], A0.x, B3.x); fma2(acc[0][3], A0.y, B3.y);
        fma2(acc[1][0], A1.x, B0.x); fma2(acc[1][0], A1.y, B0.y);
        fma2(acc[1][1], A1.x, B1.x); fma2(acc[1][1], A1.y, B1.y);
        fma2(acc[1][2], A1.x, B2.x); fma2(acc[1][2], A1.y, B2.y);
        fma2(acc[1][3], A1.x, B3.x); fma2(acc[1][3], A1.y, B3.y);
    }

    float bj[4];
    #pragma unroll
    for (int j = 0; j < 4; j++) bj[j] = __ldg(b + tx + 16 * j);

    #pragma unroll
    for (int r = 0; r < 2; r++) {
        int node = base + 2 * ty + r;
        if (node < N) {
            #pragma unroll
            for (int j = 0; j < 4; j++) {
                float2 p = upk2(acc[r][j]);
                out[(size_t)node * 64 + tx + 16 * j] = p.x + p.y + bj[j];
            }
        }
    }
}

extern "C" void kernel_launch(void* const* d_in, const int* in_sizes, int n_in,
                              void* d_out, int out_size)
{
    const float* x      = (const float*)d_in[0];
    const int*   row    = (const int*)  d_in[1];
    const int*   colptr = (const int*)  d_in[2];
    const float* W      = (const float*)d_in[3];
    const float* b      = (const float*)d_in[4];
    float*       out    = (float*)d_out;

    const int N = in_sizes[2] - 1;   // 100000

    cudaFuncSetAttribute(sage_fused_kernel,
                         cudaFuncAttributeMaxDynamicSharedMemorySize,
                         SMEM_BYTES);

    int grid = (N + NPB - 1) / NPB;
    sage_fused_kernel<<<grid, THREADS, SMEM_BYTES>>>(x, row, colptr, W, b, out, N);
}

// round 3
// speedup vs baseline: 1.2962x; 1.2198x over previous
#include <cuda_runtime.h>

// CuGraphSAGEConv, two-kernel pipeline:
//   K1 gather: agg[j] = mean_{e in [colptr[j],colptr[j+1])} x[row[e]]   (scratch)
//   K2 gemm:   out = [agg | x] @ W^T + b
//
// K1: no smem, 16-lane group per node, 4-edge unroll + row-index prefetch
//     -> pure MLP machine against L2.
// K2: 256-node x 64-out block tile, 8x8 per-thread tile with f32x2
//     node-pair packed accumulators (FFMA2), k-major smem staging.

#define D_IN  64
#define DK    128
#define D_OUT 64

#define NPAD  100352                     // >= ceil(N/256)*256 for N=100000
__device__ float g_agg[(size_t)NPAD * D_IN];

// ---- packed f32x2 helpers ----
__device__ __forceinline__ unsigned long long pk2(float a, float c) {
    unsigned long long d;
    asm("mov.b64 %0, {%1,%2};" : "=l"(d) : "f"(a), "f"(c));
    return d;
}
__device__ __forceinline__ unsigned long long pk2dup(float a) {
    unsigned long long d;
    asm("mov.b64 %0, {%1,%1};" : "=l"(d) : "f"(a));
    return d;
}
__device__ __forceinline__ void fma2(unsigned long long& c,
                                     unsigned long long a,
                                     unsigned long long b) {
    asm("fma.rn.f32x2 %0, %1, %2, %0;" : "+l"(c) : "l"(a), "l"(b));
}
__device__ __forceinline__ float2 upk2(unsigned long long d) {
    float2 r;
    asm("mov.b64 {%0,%1}, %2;" : "=f"(r.x), "=f"(r.y) : "l"(d));
    return r;
}

// ============================ K1: gather ============================
__global__ __launch_bounds__(256)
void gather_kernel(const float4* __restrict__ x4,
                   const int*    __restrict__ row,
                   const int*    __restrict__ colptr,
                   int N)
{
    const int g  = (blockIdx.x * 256 + threadIdx.x) >> 4;  // node id
    const int gl = threadIdx.x & 15;
    if (g >= N) return;

    const int e0 = __ldg(colptr + g);
    const int e1 = __ldg(colptr + g + 1);

    float4 acc = make_float4(0.f, 0.f, 0.f, 0.f);
    int e = e0;
    if (e + 4 <= e1) {
        int sa0 = __ldg(row + e);
        int sa1 = __ldg(row + e + 1);
        int sa2 = __ldg(row + e + 2);
        int sa3 = __ldg(row + e + 3);
        e += 4;
        for (; e + 4 <= e1; e += 4) {
            // prefetch next chunk's indices before using current values
            int sb0 = __ldg(row + e);
            int sb1 = __ldg(row + e + 1);
            int sb2 = __ldg(row + e + 2);
            int sb3 = __ldg(row + e + 3);
            float4 v0 = __ldg(x4 + (size_t)sa0 * 16 + gl);
            float4 v1 = __ldg(x4 + (size_t)sa1 * 16 + gl);
            float4 v2 = __ldg(x4 + (size_t)sa2 * 16 + gl);
            float4 v3 = __ldg(x4 + (size_t)sa3 * 16 + gl);
            acc.x += (v0.x + v1.x) + (v2.x + v3.x);
            acc.y += (v0.y + v1.y) + (v2.y + v3.y);
            acc.z += (v0.z + v1.z) + (v2.z + v3.z);
            acc.w += (v0.w + v1.w) + (v2.w + v3.w);
            sa0 = sb0; sa1 = sb1; sa2 = sb2; sa3 = sb3;
        }
        float4 v0 = __ldg(x4 + (size_t)sa0 * 16 + gl);
        float4 v1 = __ldg(x4 + (size_t)sa1 * 16 + gl);
        float4 v2 = __ldg(x4 + (size_t)sa2 * 16 + gl);
        float4 v3 = __ldg(x4 + (size_t)sa3 * 16 + gl);
        acc.x += (v0.x + v1.x) + (v2.x + v3.x);
        acc.y += (v0.y + v1.y) + (v2.y + v3.y);
        acc.z += (v0.z + v1.z) + (v2.z + v3.z);
        acc.w += (v0.w + v1.w) + (v2.w + v3.w);
    }
    for (; e < e1; e++) {
        int s = __ldg(row + e);
        float4 v = __ldg(x4 + (size_t)s * 16 + gl);
        acc.x += v.x; acc.y += v.y; acc.z += v.z; acc.w += v.w;
    }

    const int deg = e1 - e0;
    const float inv = 1.f / (float)(deg > 0 ? deg : 1);
    acc.x *= inv; acc.y *= inv; acc.z *= inv; acc.w *= inv;

    reinterpret_cast<float4*>(g_agg)[(size_t)g * 16 + gl] = acc;
}

// ============================ K2: gemm ============================
#define NB   256     // nodes per block
#define LDW  68      // floats per k-row of staged W
#define LDA  130     // ull (node-pairs + pad) per k-row of staged A chunk

static const int GEMM_SMEM = 64 * LDA * 8 + DK * LDW * 4;  // 66560+34816=101376

extern __shared__ char g_sm[];

__global__ __launch_bounds__(256, 2)
void gemm_kernel(const float* __restrict__ x,
                 const float* __restrict__ W,
                 const float* __restrict__ b,
                 float*       __restrict__ out,
                 int N)
{
    unsigned long long* Aq = reinterpret_cast<unsigned long long*>(g_sm); // [64][LDA]
    float* Wt = reinterpret_cast<float*>(g_sm + 64 * LDA * 8);            // [128][LDW]

    const int t    = threadIdx.x;
    const int base = blockIdx.x * NB;

    // stage W k-major: Wt[k][o] = W[o*128 + k]
    #pragma unroll
    for (int i = t; i < D_OUT * DK; i += 256) {
        int o = i >> 7, k = i & 127;
        Wt[k * LDW + o] = W[i];
    }

    const int to  = t & 7;    // out group:   o = 8*to .. 8*to+7
    const int tnp = t >> 3;   // node-pair group: np = 4*tnp .. +3 (nodes 8*tnp..+7)

    unsigned long long acc[4][8];
    #pragma unroll
    for (int i = 0; i < 4; i++)
        #pragma unroll
        for (int j = 0; j < 8; j++) acc[i][j] = 0ull;

    // A-tile loader mapping: thread handles node pair (2*tt, 2*tt+1), q-half qh
    const int tt = t & 127;
    const int qh = t >> 7;

    #pragma unroll 1
    for (int chunk = 0; chunk < 2; chunk++) {
        const float4* s4 = reinterpret_cast<const float4*>(chunk ? x : g_agg);
        if (chunk) __syncthreads();   // previous chunk's reads done

        {
            int n0 = base + 2 * tt;
            int m0 = min(n0, N - 1);
            int m1 = min(n0 + 1, N - 1);
            #pragma unroll
            for (int qq = 0; qq < 8; qq++) {
                int q = 8 * qh + qq;
                float4 a = __ldg(s4 + (size_t)m0 * 16 + q);
                float4 c = __ldg(s4 + (size_t)m1 * 16 + q);
                Aq[(4 * q + 0) * LDA + tt] = pk2(a.x, c.x);
                Aq[(4 * q + 1) * LDA + tt] = pk2(a.y, c.y);
                Aq[(4 * q + 2) * LDA + tt] = pk2(a.z, c.z);
                Aq[(4 * q + 3) * LDA + tt] = pk2(a.w, c.w);
            }
        }
        __syncthreads();

        const int kw0 = chunk * 64;
        #pragma unroll 4
        for (int k = 0; k < 64; k++) {
            ulonglong2 a01 = *reinterpret_cast<const ulonglong2*>(Aq + k * LDA + 4 * tnp);
            ulonglong2 a23 = *reinterpret_cast<const ulonglong2*>(Aq + k * LDA + 4 * tnp + 2);
            const float* wr = Wt + (kw0 + k) * LDW + 8 * to;
            float4 w0 = *reinterpret_cast<const float4*>(wr);
            float4 w1 = *reinterpret_cast<const float4*>(wr + 4);
            unsigned long long d0 = pk2dup(w0.x), d1 = pk2dup(w0.y);
            unsigned long long d2 = pk2dup(w0.z), d3 = pk2dup(w0.w);
            unsigned long long d4 = pk2dup(w1.x), d5 = pk2dup(w1.y);
            unsigned long long d6 = pk2dup(w1.z), d7 = pk2dup(w1.w);
            fma2(acc[0][0], a01.x, d0); fma2(acc[0][1], a01.x, d1);
            fma2(acc[0][2], a01.x, d2); fma2(acc[0][3], a01.x, d3);
            fma2(acc[0][4], a01.x, d4); fma2(acc[0][5], a01.x, d5);
            fma2(acc[0][6], a01.x, d6); fma2(acc[0][7], a01.x, d7);
            fma2(acc[1][0], a01.y, d0); fma2(acc[1][1], a01.y, d1);
            fma2(acc[1][2], a01.y, d2); fma2(acc[1][3], a01.y, d3);
            fma2(acc[1][4], a01.y, d4); fma2(acc[1][5], a01.y, d5);
            fma2(acc[1][6], a01.y, d6); fma2(acc[1][7], a01.y, d7);
            fma2(acc[2][0], a23.x, d0); fma2(acc[2][1], a23.x, d1);
            fma2(acc[2][2], a23.x, d2); fma2(acc[2][3], a23.x, d3);
            fma2(acc[2][4], a23.x, d4); fma2(acc[2][5], a23.x, d5);
            fma2(acc[2][6], a23.x, d6); fma2(acc[2][7], a23.x, d7);
            fma2(acc[3][0], a23.y, d0); fma2(acc[3][1], a23.y, d1);
            fma2(acc[3][2], a23.y, d2); fma2(acc[3][3], a23.y, d3);
            fma2(acc[3][4], a23.y, d4); fma2(acc[3][5], a23.y, d5);
            fma2(acc[3][6], a23.y, d6); fma2(acc[3][7], a23.y, d7);
        }
    }

    // epilogue: bias + store
    float4 b0 = *reinterpret_cast<const float4*>(b + 8 * to);
    float4 b1 = *reinterpret_cast<const float4*>(b + 8 * to + 4);
    #pragma unroll
    for (int i = 0; i < 4; i++) {
        int np = 4 * tnp + i;
        float2 r0 = upk2(acc[i][0]), r1 = upk2(acc[i][1]);
        float2 r2 = upk2(acc[i][2]), r3 = upk2(acc[i][3]);
        float2 r4 = upk2(acc[i][4]), r5 = upk2(acc[i][5]);
        float2 r6 = upk2(acc[i][6]), r7 = upk2(acc[i][7]);
        int n0 = base + 2 * np;
        if (n0 < N) {
            float4 o0 = make_float4(r0.x + b0.x, r1.x + b0.y, r2.x + b0.z, r3.x + b0.w);
            float4 o1 = make_float4(r4.x + b1.x, r5.x + b1.y, r6.x + b1.z, r7.x + b1.w);
            float4* op = reinterpret_cast<float4*>(out + (size_t)n0 * D_OUT + 8 * to);
            op[0] = o0; op[1] = o1;
        }
        int n1 = n0 + 1;
        if (n1 < N) {
            float4 o0 = make_float4(r0.y + b0.x, r1.y + b0.y, r2.y + b0.z, r3.y + b0.w);
            float4 o1 = make_float4(r4.y + b1.x, r5.y + b1.y, r6.y + b1.z, r7.y + b1.w);
            float4* op = reinterpret_cast<float4*>(out + (size_t)n1 * D_OUT + 8 * to);
            op[0] = o0; op[1] = o1;
        }
    }
}

// ============================ launch ============================
extern "C" void kernel_launch(void* const* d_in, const int* in_sizes, int n_in,
                              void* d_out, int out_size)
{
    const float* x      = (const float*)d_in[0];
    const int*   row    = (const int*)  d_in[1];
    const int*   colptr = (const int*)  d_in[2];
    const float* W      = (const float*)d_in[3];
    const float* b      = (const float*)d_in[4];
    float*       out    = (float*)d_out;

    const int N = in_sizes[2] - 1;   // 100000

    cudaFuncSetAttribute(gemm_kernel,
                         cudaFuncAttributeMaxDynamicSharedMemorySize,
                         GEMM_SMEM);

    int gather_grid = (N * 16 + 255) / 256;
    gather_kernel<<<gather_grid, 256>>>(
        reinterpret_cast<const float4*>(x), row, colptr, N);

    int gemm_grid = (N + NB - 1) / NB;
    gemm_kernel<<<gemm_grid, 256, GEMM_SMEM>>>(x, W, b, out, N);
}

// round 5
// speedup vs baseline: 1.5330x; 1.1827x over previous
#include <cuda_runtime.h>
#include <cuda_bf16.h>
#include <cstdint>

// CuGraphSAGEConv, two-kernel pipeline:
//   K1 gather: agg[j] = mean_{e in [colptr[j],colptr[j+1])} x[row[e]]
//   K2 gemm:   out = [agg | x] @ W^T + b   via mma.sync bf16 3-pass split
//              (compute_100-safe: no tcgen05)

#define D_IN  64
#define DK    128
#define D_OUT 64

#define NPAD  100352
__device__ float g_agg[(size_t)NPAD * D_IN];

// ======================= helpers =======================
__device__ __forceinline__ uint32_t smem_u32(const void* p) {
    uint32_t a;
    asm("{ .reg .u64 t; cvta.to.shared.u64 t, %1; cvt.u32.u64 %0, t; }"
        : "=r"(a) : "l"(p));
    return a;
}
// two floats -> {packed hi bf16x2, packed lo bf16x2}
__device__ __forceinline__ uint2 split2(float v0, float v1) {
    __nv_bfloat16 h0 = __float2bfloat16_rn(v0);
    __nv_bfloat16 h1 = __float2bfloat16_rn(v1);
    float r0 = v0 - __bfloat162float(h0);
    float r1 = v1 - __bfloat162float(h1);
    __nv_bfloat162 hh = __halves2bfloat162(h0, h1);
    __nv_bfloat162 ll = __halves2bfloat162(__float2bfloat16_rn(r0),
                                           __float2bfloat16_rn(r1));
    uint2 r;
    r.x = *reinterpret_cast<uint32_t*>(&hh);
    r.y = *reinterpret_cast<uint32_t*>(&ll);
    return r;
}
__device__ __forceinline__ void ldm_x4(uint4& r, uint32_t addr) {
    asm volatile("ldmatrix.sync.aligned.m8n8.x4.shared.b16 {%0,%1,%2,%3}, [%4];"
                 : "=r"(r.x), "=r"(r.y), "=r"(r.z), "=r"(r.w) : "r"(addr));
}
__device__ __forceinline__ void mma16816(float* c, const uint4& a,
                                         uint32_t b0, uint32_t b1) {
    asm volatile(
        "mma.sync.aligned.m16n8k16.row.col.f32.bf16.bf16.f32 "
        "{%0,%1,%2,%3}, {%4,%5,%6,%7}, {%8,%9}, {%0,%1,%2,%3};"
        : "+f"(c[0]), "+f"(c[1]), "+f"(c[2]), "+f"(c[3])
        : "r"(a.x), "r"(a.y), "r"(a.z), "r"(a.w), "r"(b0), "r"(b1));
}

// ======================= K1: gather =======================
__global__ __launch_bounds__(256)
void gather_kernel(const float4* __restrict__ x4,
                   const int*    __restrict__ row,
                   const int*    __restrict__ colptr,
                   int N)
{
    const int g  = (blockIdx.x * 256 + threadIdx.x) >> 4;
    const int gl = threadIdx.x & 15;
    if (g >= N) return;

    const int e0 = __ldg(colptr + g);
    const int e1 = __ldg(colptr + g + 1);

    float4 acc = make_float4(0.f, 0.f, 0.f, 0.f);
    int e = e0;
    if (e + 4 <= e1) {
        int sa0 = __ldg(row + e), sa1 = __ldg(row + e + 1);
        int sa2 = __ldg(row + e + 2), sa3 = __ldg(row + e + 3);
        e += 4;
        for (; e + 4 <= e1; e += 4) {
            int sb0 = __ldg(row + e),     sb1 = __ldg(row + e + 1);
            int sb2 = __ldg(row + e + 2), sb3 = __ldg(row + e + 3);
            float4 v0 = __ldg(x4 + (size_t)sa0 * 16 + gl);
            float4 v1 = __ldg(x4 + (size_t)sa1 * 16 + gl);
            float4 v2 = __ldg(x4 + (size_t)sa2 * 16 + gl);
            float4 v3 = __ldg(x4 + (size_t)sa3 * 16 + gl);
            acc.x += (v0.x + v1.x) + (v2.x + v3.x);
            acc.y += (v0.y + v1.y) + (v2.y + v3.y);
            acc.z += (v0.z + v1.z) + (v2.z + v3.z);
            acc.w += (v0.w + v1.w) + (v2.w + v3.w);
            sa0 = sb0; sa1 = sb1; sa2 = sb2; sa3 = sb3;
        }
        float4 v0 = __ldg(x4 + (size_t)sa0 * 16 + gl);
        float4 v1 = __ldg(x4 + (size_t)sa1 * 16 + gl);
        float4 v2 = __ldg(x4 + (size_t)sa2 * 16 + gl);
        float4 v3 = __ldg(x4 + (size_t)sa3 * 16 + gl);
        acc.x += (v0.x + v1.x) + (v2.x + v3.x);
        acc.y += (v0.y + v1.y) + (v2.y + v3.y);
        acc.z += (v0.z + v1.z) + (v2.z + v3.z);
        acc.w += (v0.w + v1.w) + (v2.w + v3.w);
    }
    for (; e < e1; e++) {
        int s = __ldg(row + e);
        float4 v = __ldg(x4 + (size_t)s * 16 + gl);
        acc.x += v.x; acc.y += v.y; acc.z += v.z; acc.w += v.w;
    }
    const int deg = e1 - e0;
    const float inv = 1.f / (float)(deg > 0 ? deg : 1);
    acc.x *= inv; acc.y *= inv; acc.z *= inv; acc.w *= inv;
    reinterpret_cast<float4*>(g_agg)[(size_t)g * 16 + gl] = acc;
}

// ======================= K2: HMMA GEMM =======================
#define GB   128        // nodes per block
#define ROWB 272        // 136 bf16 per row (padded; 272 % 128 = 16 -> conflict-free)
#define SM_AHI 0
#define SM_ALO 34816    // 128*272
#define SM_WHI 69632
#define SM_WLO 87040    // + 64*272
#define SM_TOT 104448

extern __shared__ char g_sm[];

__global__ __launch_bounds__(256, 2)
void gemm_mma_kernel(const float* __restrict__ x,
                     const float* __restrict__ W,
                     const float* __restrict__ b,
                     float*       __restrict__ out,
                     int N)
{
    const uint32_t sb = smem_u32(g_sm);
    const int tid  = threadIdx.x;
    const int wid  = tid >> 5;
    const int lane = tid & 31;
    const int base = blockIdx.x * GB;

    // ---- stage A (feat = [agg | x]) hi/lo, [m][k] padded rows ----
    {
        const int m    = tid & 127;
        const int half = tid >> 7;                 // 0: agg k0..63, 1: x k64..127
        const int mg   = min(base + m, N - 1);
        const float4* src = reinterpret_cast<const float4*>(half ? x : g_agg)
                            + (size_t)mg * 16;
        char* dhi = g_sm + SM_AHI + m * ROWB + half * 128;
        char* dlo = g_sm + SM_ALO + m * ROWB + half * 128;
        #pragma unroll
        for (int i = 0; i < 8; i++) {
            float4 f0 = __ldg(src + 2 * i);
            float4 f1 = __ldg(src + 2 * i + 1);
            uint2 p0 = split2(f0.x, f0.y);
            uint2 p1 = split2(f0.z, f0.w);
            uint2 p2 = split2(f1.x, f1.y);
            uint2 p3 = split2(f1.z, f1.w);
            *reinterpret_cast<uint4*>(dhi + i * 16) = make_uint4(p0.x, p1.x, p2.x, p3.x);
            *reinterpret_cast<uint4*>(dlo + i * 16) = make_uint4(p0.y, p1.y, p2.y, p3.y);
        }
    }
    // ---- stage W hi/lo, [o][k] padded rows (natural layout) ----
    {
        const int o  = tid & 63;
        const int kq = tid >> 6;                   // 0..3 -> k 32*kq..+31
        const float4* wsrc = reinterpret_cast<const float4*>(W)
                             + (size_t)o * 32 + kq * 8;
        char* dhi = g_sm + SM_WHI + o * ROWB + kq * 64;
        char* dlo = g_sm + SM_WLO + o * ROWB + kq * 64;
        #pragma unroll
        for (int i = 0; i < 4; i++) {
            float4 f0 = __ldg(wsrc + 2 * i);
            float4 f1 = __ldg(wsrc + 2 * i + 1);
            uint2 p0 = split2(f0.x, f0.y);
            uint2 p1 = split2(f0.z, f0.w);
            uint2 p2 = split2(f1.x, f1.y);
            uint2 p3 = split2(f1.z, f1.w);
            *reinterpret_cast<uint4*>(dhi + i * 16) = make_uint4(p0.x, p1.x, p2.x, p3.x);
            *reinterpret_cast<uint4*>(dlo + i * 16) = make_uint4(p0.y, p1.y, p2.y, p3.y);
        }
    }
    __syncthreads();

    // warp grid: 4 m-warps x 2 n-warps; warp tile 32 nodes x 32 outs
    const int wm = wid >> 1;
    const int wn = wid & 1;

    // ldmatrix lane->address bases
    // A (x4 over 16x16): lanes: row = lane&15, k-half = lane>>4
    const uint32_t a_base = sb + SM_AHI
        + (uint32_t)(wm * 32 + (lane & 15)) * ROWB + (uint32_t)(lane >> 4) * 16;
    // B (x4 over 16 n-rows x 16 k): row = ((lane>>4)<<3)+(lane&7), k-chunk = (lane>>3)&1
    const int brow = wn * 32 + ((lane >> 4) << 3) + (lane & 7);
    const uint32_t b_base = sb + SM_WHI
        + (uint32_t)brow * ROWB + (uint32_t)((lane >> 3) & 1) * 16;

    float acc[2][4][4];
    #pragma unroll
    for (int i = 0; i < 2; i++)
        #pragma unroll
        for (int j = 0; j < 4; j++)
            #pragma unroll
            for (int q = 0; q < 4; q++) acc[i][j][q] = 0.f;

    #pragma unroll
    for (int ks = 0; ks < 8; ks++) {
        const uint32_t ao = a_base + ks * 32;
        const uint32_t bo = b_base + ks * 32;
        uint4 ah0, ah1, al0, al1, bh0, bh1, bl0, bl1;
        ldm_x4(ah0, ao);
        ldm_x4(ah1, ao + 16 * ROWB);
        ldm_x4(al0, ao + (SM_ALO - SM_AHI));
        ldm_x4(al1, ao + (SM_ALO - SM_AHI) + 16 * ROWB);
        ldm_x4(bh0, bo);
        ldm_x4(bh1, bo + 16 * ROWB);
        ldm_x4(bl0, bo + (SM_WLO - SM_WHI));
        ldm_x4(bl1, bo + (SM_WLO - SM_WHI) + 16 * ROWB);

        // pass 1: Ahi * Bhi
        mma16816(acc[0][0], ah0, bh0.x, bh0.y);
        mma16816(acc[0][1], ah0, bh0.z, bh0.w);
        mma16816(acc[0][2], ah0, bh1.x, bh1.y);
        mma16816(acc[0][3], ah0, bh1.z, bh1.w);
        mma16816(acc[1][0], ah1, bh0.x, bh0.y);
        mma16816(acc[1][1], ah1, bh0.z, bh0.w);
        mma16816(acc[1][2], ah1, bh1.x, bh1.y);
        mma16816(acc[1][3], ah1, bh1.z, bh1.w);
        // pass 2: Ahi * Blo
        mma16816(acc[0][0], ah0, bl0.x, bl0.y);
        mma16816(acc[0][1], ah0, bl0.z, bl0.w);
        mma16816(acc[0][2], ah0, bl1.x, bl1.y);
        mma16816(acc[0][3], ah0, bl1.z, bl1.w);
        mma16816(acc[1][0], ah1, bl0.x, bl0.y);
        mma16816(acc[1][1], ah1, bl0.z, bl0.w);
        mma16816(acc[1][2], ah1, bl1.x, bl1.y);
        mma16816(acc[1][3], ah1, bl1.z, bl1.w);
        // pass 3: Alo * Bhi
        mma16816(acc[0][0], al0, bh0.x, bh0.y);
        mma16816(acc[0][1], al0, bh0.z, bh0.w);
        mma16816(acc[0][2], al0, bh1.x, bh1.y);
        mma16816(acc[0][3], al0, bh1.z, bh1.w);
        mma16816(acc[1][0], al1, bh0.x, bh0.y);
        mma16816(acc[1][1], al1, bh0.z, bh0.w);
        mma16816(acc[1][2], al1, bh1.x, bh1.y);
        mma16816(acc[1][3], al1, bh1.z, bh1.w);
    }

    // ---- epilogue ----
    const int g   = lane >> 2;
    const int tig = lane & 3;
    float2 bb[4];
    #pragma unroll
    for (int ns = 0; ns < 4; ns++) {
        int col = wn * 32 + ns * 8 + 2 * tig;
        bb[ns] = make_float2(__ldg(b + col), __ldg(b + col + 1));
    }
    #pragma unroll
    for (int ms = 0; ms < 2; ms++) {
        const int node0 = base + wm * 32 + ms * 16 + g;
        const int node1 = node0 + 8;
        #pragma unroll
        for (int ns = 0; ns < 4; ns++) {
            const int col = wn * 32 + ns * 8 + 2 * tig;
            if (node0 < N) {
                *reinterpret_cast<float2*>(out + (size_t)node0 * D_OUT + col) =
                    make_float2(acc[ms][ns][0] + bb[ns].x, acc[ms][ns][1] + bb[ns].y);
            }
            if (node1 < N) {
                *reinterpret_cast<float2*>(out + (size_t)node1 * D_OUT + col) =
                    make_float2(acc[ms][ns][2] + bb[ns].x, acc[ms][ns][3] + bb[ns].y);
            }
        }
    }
}

// ======================= launch =======================
extern "C" void kernel_launch(void* const* d_in, const int* in_sizes, int n_in,
                              void* d_out, int out_size)
{
    const float* x      = (const float*)d_in[0];
    const int*   row    = (const int*)  d_in[1];
    const int*   colptr = (const int*)  d_in[2];
    const float* W      = (const float*)d_in[3];
    const float* b      = (const float*)d_in[4];
    float*       out    = (float*)d_out;

    const int N = in_sizes[2] - 1;   // 100000

    cudaFuncSetAttribute(gemm_mma_kernel,
                         cudaFuncAttributeMaxDynamicSharedMemorySize, SM_TOT);

    int gather_grid = (N * 16 + 255) / 256;
    gather_kernel<<<gather_grid, 256>>>(
        reinterpret_cast<const float4*>(x), row, colptr, N);

    int gemm_grid = (N + GB - 1) / GB;
    gemm_mma_kernel<<<gemm_grid, 256, SM_TOT>>>(x, W, b, out, N);
}

// round 6
// speedup vs baseline: 1.6346x; 1.0662x over previous
#include <cuda_runtime.h>
#include <cuda_bf16.h>
#include <cuda_fp16.h>
#include <cstdint>

// CuGraphSAGEConv pipeline:
//   K0a convert_x: x(f32) -> g_xh(fp16, for gather) + feat x_hi/x_lo(bf16)
//   K0b convert_w: W(f32) -> g_wcvt bf16 hi/lo rows
//   K1  gather:    agg = mean of fp16 neighbors (f32 accum) -> feat agg_hi/agg_lo
//   K2  gemm:      out = [agg|x] @ W^T + b, mma.sync bf16 3-pass split,
//                  staging via cp.async from pre-converted scratch.

#define D_IN  64
#define DK    128
#define D_OUT 64

#define NPAD  100352
// feat row (512B): [agg_hi 128B | x_hi 128B | agg_lo 128B | x_lo 128B]
__device__ unsigned char g_feat[(size_t)NPAD * 512];
__device__ __half        g_xh[(size_t)NPAD * D_IN];
__device__ unsigned char g_wcvt[64 * 512];   // [w_hi 256B | w_lo 256B] per out row

// ======================= helpers =======================
__device__ __forceinline__ uint32_t smem_u32(const void* p) {
    uint32_t a;
    asm("{ .reg .u64 t; cvta.to.shared.u64 t, %1; cvt.u32.u64 %0, t; }"
        : "=r"(a) : "l"(p));
    return a;
}
__device__ __forceinline__ uint2 split2(float v0, float v1) {
    __nv_bfloat16 h0 = __float2bfloat16_rn(v0);
    __nv_bfloat16 h1 = __float2bfloat16_rn(v1);
    float r0 = v0 - __bfloat162float(h0);
    float r1 = v1 - __bfloat162float(h1);
    __nv_bfloat162 hh = __halves2bfloat162(h0, h1);
    __nv_bfloat162 ll = __halves2bfloat162(__float2bfloat16_rn(r0),
                                           __float2bfloat16_rn(r1));
    uint2 r;
    r.x = *reinterpret_cast<uint32_t*>(&hh);
    r.y = *reinterpret_cast<uint32_t*>(&ll);
    return r;
}
__device__ __forceinline__ void ldm_x4(uint4& r, uint32_t addr) {
    asm volatile("ldmatrix.sync.aligned.m8n8.x4.shared.b16 {%0,%1,%2,%3}, [%4];"
                 : "=r"(r.x), "=r"(r.y), "=r"(r.z), "=r"(r.w) : "r"(addr));
}
__device__ __forceinline__ void mma16816(float* c, const uint4& a,
                                         uint32_t b0, uint32_t b1) {
    asm volatile(
        "mma.sync.aligned.m16n8k16.row.col.f32.bf16.bf16.f32 "
        "{%0,%1,%2,%3}, {%4,%5,%6,%7}, {%8,%9}, {%0,%1,%2,%3};"
        : "+f"(c[0]), "+f"(c[1]), "+f"(c[2]), "+f"(c[3])
        : "r"(a.x), "r"(a.y), "r"(a.z), "r"(a.w), "r"(b0), "r"(b1));
}
__device__ __forceinline__ void cp16(uint32_t dst, const void* src) {
    asm volatile("cp.async.cg.shared.global [%0], [%1], 16;"
                 :: "r"(dst), "l"(src));
}

// ======================= K0a: convert x =======================
__global__ __launch_bounds__(256)
void convert_x_kernel(const float4* __restrict__ x4, int N)
{
    const int idx  = blockIdx.x * 256 + threadIdx.x;
    const int node = idx >> 4;
    const int gl   = idx & 15;
    if (node >= NPAD) return;

    float4 v = make_float4(0.f, 0.f, 0.f, 0.f);
    if (node < N) v = __ldg(x4 + (size_t)node * 16 + gl);

    // fp16 for gather
    __half2 h01 = __floats2half2_rn(v.x, v.y);
    __half2 h23 = __floats2half2_rn(v.z, v.w);
    uint2 hp;
    hp.x = *reinterpret_cast<uint32_t*>(&h01);
    hp.y = *reinterpret_cast<uint32_t*>(&h23);
    reinterpret_cast<uint2*>(g_xh)[(size_t)node * 16 + gl] = hp;

    // bf16 hi/lo for GEMM (x half of feat row)
    uint2 p0 = split2(v.x, v.y);
    uint2 p1 = split2(v.z, v.w);
    unsigned char* fr = g_feat + (size_t)node * 512;
    *reinterpret_cast<uint2*>(fr + 128 + gl * 8) = make_uint2(p0.x, p1.x);
    *reinterpret_cast<uint2*>(fr + 384 + gl * 8) = make_uint2(p0.y, p1.y);
}

// ======================= K0b: convert W =======================
__global__ __launch_bounds__(256)
void convert_w_kernel(const float4* __restrict__ W4)
{
    const int idx = blockIdx.x * 256 + threadIdx.x;   // 0..2047
    if (idx >= 64 * 32) return;
    const int o = idx >> 5;
    const int q = idx & 31;
    float4 v = __ldg(W4 + idx);
    uint2 p0 = split2(v.x, v.y);
    uint2 p1 = split2(v.z, v.w);
    unsigned char* wr = g_wcvt + (size_t)o * 512;
    *reinterpret_cast<uint2*>(wr + q * 8)       = make_uint2(p0.x, p1.x);
    *reinterpret_cast<uint2*>(wr + 256 + q * 8) = make_uint2(p0.y, p1.y);
}

// ======================= K1: gather (fp16 reads) =======================
__device__ __forceinline__ void acc_h(float4& a, uint2 h) {
    __half2 h01 = *reinterpret_cast<__half2*>(&h.x);
    __half2 h23 = *reinterpret_cast<__half2*>(&h.y);
    float2 f01 = __half22float2(h01);
    float2 f23 = __half22float2(h23);
    a.x += f01.x; a.y += f01.y; a.z += f23.x; a.w += f23.y;
}

__global__ __launch_bounds__(256)
void gather_kernel(const int* __restrict__ row,
                   const int* __restrict__ colptr,
                   int N)
{
    const int g  = (blockIdx.x * 256 + threadIdx.x) >> 4;
    const int gl = threadIdx.x & 15;
    if (g >= N) return;

    const uint2* xh2 = reinterpret_cast<const uint2*>(g_xh);

    const int e0 = __ldg(colptr + g);
    const int e1 = __ldg(colptr + g + 1);

    float4 acc = make_float4(0.f, 0.f, 0.f, 0.f);
    int e = e0;
    if (e + 4 <= e1) {
        int sa0 = __ldg(row + e), sa1 = __ldg(row + e + 1);
        int sa2 = __ldg(row + e + 2), sa3 = __ldg(row + e + 3);
        e += 4;
        for (; e + 4 <= e1; e += 4) {
            int sb0 = __ldg(row + e),     sb1 = __ldg(row + e + 1);
            int sb2 = __ldg(row + e + 2), sb3 = __ldg(row + e + 3);
            uint2 v0 = __ldg(xh2 + (size_t)sa0 * 16 + gl);
            uint2 v1 = __ldg(xh2 + (size_t)sa1 * 16 + gl);
            uint2 v2 = __ldg(xh2 + (size_t)sa2 * 16 + gl);
            uint2 v3 = __ldg(xh2 + (size_t)sa3 * 16 + gl);
            acc_h(acc, v0); acc_h(acc, v1); acc_h(acc, v2); acc_h(acc, v3);
            sa0 = sb0; sa1 = sb1; sa2 = sb2; sa3 = sb3;
        }
        uint2 v0 = __ldg(xh2 + (size_t)sa0 * 16 + gl);
        uint2 v1 = __ldg(xh2 + (size_t)sa1 * 16 + gl);
        uint2 v2 = __ldg(xh2 + (size_t)sa2 * 16 + gl);
        uint2 v3 = __ldg(xh2 + (size_t)sa3 * 16 + gl);
        acc_h(acc, v0); acc_h(acc, v1); acc_h(acc, v2); acc_h(acc, v3);
    }
    for (; e < e1; e++) {
        int s = __ldg(row + e);
        uint2 v = __ldg(xh2 + (size_t)s * 16 + gl);
        acc_h(acc, v);
    }
    const int deg = e1 - e0;
    const float inv = 1.f / (float)(deg > 0 ? deg : 1);
    acc.x *= inv; acc.y *= inv; acc.z *= inv; acc.w *= inv;

    uint2 p0 = split2(acc.x, acc.y);
    uint2 p1 = split2(acc.z, acc.w);
    unsigned char* fr = g_feat + (size_t)g * 512;
    *reinterpret_cast<uint2*>(fr + gl * 8)       = make_uint2(p0.x, p1.x);
    *reinterpret_cast<uint2*>(fr + 256 + gl * 8) = make_uint2(p0.y, p1.y);
}

// ======================= K2: HMMA GEMM =======================
#define GB   128
#define ROWB 272
#define SM_AHI 0
#define SM_ALO 34816
#define SM_WHI 69632
#define SM_WLO 87040
#define SM_TOT 104448

extern __shared__ char g_sm[];

__global__ __launch_bounds__(256, 2)
void gemm_mma_kernel(const float* __restrict__ b,
                     float*       __restrict__ out,
                     int N)
{
    const uint32_t sb = smem_u32(g_sm);
    const int tid  = threadIdx.x;
    const int wid  = tid >> 5;
    const int lane = tid & 31;
    const int base = blockIdx.x * GB;

    // ---- stage A via cp.async: thread = (row m, half) ----
    {
        const int m    = tid & 127;
        const int half = tid >> 7;       // 0 -> hi bytes [0,256), 1 -> lo [256,512)
        const unsigned char* src = g_feat + (size_t)(base + m) * 512 + half * 256;
        const uint32_t dst = sb + (half ? SM_ALO : SM_AHI) + m * ROWB;
        #pragma unroll
        for (int i = 0; i < 16; i++)
            cp16(dst + i * 16, src + i * 16);
    }
    // ---- stage W via cp.async: chunks c = tid + 256*j ----
    {
        #pragma unroll
        for (int j = 0; j < 8; j++) {
            const int c = tid + 256 * j;          // 0..2047
            const int o = c >> 5;
            const int q = c & 31;                 // 0..15 hi, 16..31 lo
            const unsigned char* src = g_wcvt + (size_t)o * 512 + q * 16;
            const uint32_t dst = sb + (q < 16 ? SM_WHI : SM_WLO)
                                 + o * ROWB + (q & 15) * 16;
            cp16(dst, src);
        }
    }
    asm volatile("cp.async.commit_group;" ::: "memory");
    asm volatile("cp.async.wait_group 0;" ::: "memory");
    __syncthreads();

    // warp grid: 4 m-warps x 2 n-warps; warp tile 32 nodes x 32 outs
    const int wm = wid >> 1;
    const int wn = wid & 1;

    const uint32_t a_base = sb + SM_AHI
        + (uint32_t)(wm * 32 + (lane & 15)) * ROWB + (uint32_t)(lane >> 4) * 16;
    const int brow = wn * 32 + ((lane >> 4) << 3) + (lane & 7);
    const uint32_t b_base = sb + SM_WHI
        + (uint32_t)brow * ROWB + (uint32_t)((lane >> 3) & 1) * 16;

    float acc[2][4][4];
    #pragma unroll
    for (int i = 0; i < 2; i++)
        #pragma unroll
        for (int j = 0; j < 4; j++)
            #pragma unroll
            for (int q = 0; q < 4; q++) acc[i][j][q] = 0.f;

    #pragma unroll
    for (int ks = 0; ks < 8; ks++) {
        const uint32_t ao = a_base + ks * 32;
        const uint32_t bo = b_base + ks * 32;
        uint4 ah0, ah1, al0, al1, bh0, bh1, bl0, bl1;
        ldm_x4(ah0, ao);
        ldm_x4(ah1, ao + 16 * ROWB);
        ldm_x4(al0, ao + (SM_ALO - SM_AHI));
        ldm_x4(al1, ao + (SM_ALO - SM_AHI) + 16 * ROWB);
        ldm_x4(bh0, bo);
        ldm_x4(bh1, bo + 16 * ROWB);
        ldm_x4(bl0, bo + (SM_WLO - SM_WHI));
        ldm_x4(bl1, bo + (SM_WLO - SM_WHI) + 16 * ROWB);

        mma16816(acc[0][0], ah0, bh0.x, bh0.y);
        mma16816(acc[0][1], ah0, bh0.z, bh0.w);
        mma16816(acc[0][2], ah0, bh1.x, bh1.y);
        mma16816(acc[0][3], ah0, bh1.z, bh1.w);
        mma16816(acc[1][0], ah1, bh0.x, bh0.y);
        mma16816(acc[1][1], ah1, bh0.z, bh0.w);
        mma16816(acc[1][2], ah1, bh1.x, bh1.y);
        mma16816(acc[1][3], ah1, bh1.z, bh1.w);

        mma16816(acc[0][0], ah0, bl0.x, bl0.y);
        mma16816(acc[0][1], ah0, bl0.z, bl0.w);
        mma16816(acc[0][2], ah0, bl1.x, bl1.y);
        mma16816(acc[0][3], ah0, bl1.z, bl1.w);
        mma16816(acc[1][0], ah1, bl0.x, bl0.y);
        mma16816(acc[1][1], ah1, bl0.z, bl0.w);
        mma16816(acc[1][2], ah1, bl1.x, bl1.y);
        mma16816(acc[1][3], ah1, bl1.z, bl1.w);

        mma16816(acc[0][0], al0, bh0.x, bh0.y);
        mma16816(acc[0][1], al0, bh0.z, bh0.w);
        mma16816(acc[0][2], al0, bh1.x, bh1.y);
        mma16816(acc[0][3], al0, bh1.z, bh1.w);
        mma16816(acc[1][0], al1, bh0.x, bh0.y);
        mma16816(acc[1][1], al1, bh0.z, bh0.w);
        mma16816(acc[1][2], al1, bh1.x, bh1.y);
        mma16816(acc[1][3], al1, bh1.z, bh1.w);
    }

    // ---- epilogue ----
    const int g   = lane >> 2;
    const int tig = lane & 3;
    float2 bb[4];
    #pragma unroll
    for (int ns = 0; ns < 4; ns++) {
        int col = wn * 32 + ns * 8 + 2 * tig;
        bb[ns] = make_float2(__ldg(b + col), __ldg(b + col + 1));
    }
    #pragma unroll
    for (int ms = 0; ms < 2; ms++) {
        const int node0 = base + wm * 32 + ms * 16 + g;
        const int node1 = node0 + 8;
        #pragma unroll
        for (int ns = 0; ns < 4; ns++) {
            const int col = wn * 32 + ns * 8 + 2 * tig;
            if (node0 < N) {
                *reinterpret_cast<float2*>(out + (size_t)node0 * D_OUT + col) =
                    make_float2(acc[ms][ns][0] + bb[ns].x, acc[ms][ns][1] + bb[ns].y);
            }
            if (node1 < N) {
                *reinterpret_cast<float2*>(out + (size_t)node1 * D_OUT + col) =
                    make_float2(acc[ms][ns][2] + bb[ns].x, acc[ms][ns][3] + bb[ns].y);
            }
        }
    }
}

// ======================= launch =======================
extern "C" void kernel_launch(void* const* d_in, const int* in_sizes, int n_in,
                              void* d_out, int out_size)
{
    const float* x      = (const float*)d_in[0];
    const int*   row    = (const int*)  d_in[1];
    const int*   colptr = (const int*)  d_in[2];
    const float* W      = (const float*)d_in[3];
    const float* b      = (const float*)d_in[4];
    float*       out    = (float*)d_out;

    const int N = in_sizes[2] - 1;   // 100000

    cudaFuncSetAttribute(gemm_mma_kernel,
                         cudaFuncAttributeMaxDynamicSharedMemorySize, SM_TOT);

    convert_x_kernel<<<(NPAD * 16 + 255) / 256, 256>>>(
        reinterpret_cast<const float4*>(x), N);
    convert_w_kernel<<<8, 256>>>(reinterpret_cast<const float4*>(W));

    gather_kernel<<<(N * 16 + 255) / 256, 256>>>(row, colptr, N);

    int gemm_grid = (N + GB - 1) / GB;
    gemm_mma_kernel<<<gemm_grid, 256, SM_TOT>>>(b, out, N);
}

// round 7
// speedup vs baseline: 1.6582x; 1.0145x over previous
#include <cuda_runtime.h>
#include <cuda_bf16.h>
#include <cuda_fp16.h>
#include <cstdint>

// CuGraphSAGEConv pipeline:
//   K0 convert:  x(f32) -> g_xh(fp16) + feat x_hi/x_lo(bf16); W -> g_wcvt hi/lo
//   K1 gather:   agg = mean of fp16 neighbors (HADD2 batch accum, f32 total)
//   K2 gemm:     out = [agg|x] @ W^T + b, mma.sync bf16 3-pass split,
//                2-stage cp.async pipelined staging.

#define D_IN  64
#define DK    128
#define D_OUT 64

#define NPAD  100352
// feat row (512B): [agg_hi 128B | x_hi 128B | agg_lo 128B | x_lo 128B]
__device__ unsigned char g_feat[(size_t)NPAD * 512];
__device__ __half        g_xh[(size_t)NPAD * D_IN];
__device__ unsigned char g_wcvt[64 * 512];   // [w_hi 256B | w_lo 256B] per out row

// ======================= helpers =======================
__device__ __forceinline__ uint32_t smem_u32(const void* p) {
    uint32_t a;
    asm("{ .reg .u64 t; cvta.to.shared.u64 t, %1; cvt.u32.u64 %0, t; }"
        : "=r"(a) : "l"(p));
    return a;
}
__device__ __forceinline__ uint2 split2(float v0, float v1) {
    __nv_bfloat16 h0 = __float2bfloat16_rn(v0);
    __nv_bfloat16 h1 = __float2bfloat16_rn(v1);
    float r0 = v0 - __bfloat162float(h0);
    float r1 = v1 - __bfloat162float(h1);
    __nv_bfloat162 hh = __halves2bfloat162(h0, h1);
    __nv_bfloat162 ll = __halves2bfloat162(__float2bfloat16_rn(r0),
                                           __float2bfloat16_rn(r1));
    uint2 r;
    r.x = *reinterpret_cast<uint32_t*>(&hh);
    r.y = *reinterpret_cast<uint32_t*>(&ll);
    return r;
}
__device__ __forceinline__ void ldm_x4(uint4& r, uint32_t addr) {
    asm volatile("ldmatrix.sync.aligned.m8n8.x4.shared.b16 {%0,%1,%2,%3}, [%4];"
                 : "=r"(r.x), "=r"(r.y), "=r"(r.z), "=r"(r.w) : "r"(addr));
}
__device__ __forceinline__ void mma16816(float* c, const uint4& a,
                                         uint32_t b0, uint32_t b1) {
    asm volatile(
        "mma.sync.aligned.m16n8k16.row.col.f32.bf16.bf16.f32 "
        "{%0,%1,%2,%3}, {%4,%5,%6,%7}, {%8,%9}, {%0,%1,%2,%3};"
        : "+f"(c[0]), "+f"(c[1]), "+f"(c[2]), "+f"(c[3])
        : "r"(a.x), "r"(a.y), "r"(a.z), "r"(a.w), "r"(b0), "r"(b1));
}
__device__ __forceinline__ void cp16(uint32_t dst, const void* src) {
    asm volatile("cp.async.cg.shared.global [%0], [%1], 16;"
                 :: "r"(dst), "l"(src));
}
__device__ __forceinline__ __half2 u2h(uint32_t u) {
    return *reinterpret_cast<__half2*>(&u);
}

// ======================= K0: convert x and W =======================
#define XBLOCKS 6272       // NPAD*16/256

__global__ __launch_bounds__(256)
void convert_kernel(const float4* __restrict__ x4,
                    const float4* __restrict__ W4, int N)
{
    if (blockIdx.x >= XBLOCKS) {
        // W path: 8 blocks x 256 threads = 2048 = 64 o x 32 q
        const int idx = (blockIdx.x - XBLOCKS) * 256 + threadIdx.x;
        const int o = idx >> 5;
        const int q = idx & 31;
        float4 v = __ldg(W4 + idx);
        uint2 p0 = split2(v.x, v.y);
        uint2 p1 = split2(v.z, v.w);
        unsigned char* wr = g_wcvt + (size_t)o * 512;
        *reinterpret_cast<uint2*>(wr + q * 8)       = make_uint2(p0.x, p1.x);
        *reinterpret_cast<uint2*>(wr + 256 + q * 8) = make_uint2(p0.y, p1.y);
        return;
    }
    const int idx  = blockIdx.x * 256 + threadIdx.x;
    const int node = idx >> 4;
    const int gl   = idx & 15;

    float4 v = make_float4(0.f, 0.f, 0.f, 0.f);
    if (node < N) v = __ldg(x4 + (size_t)node * 16 + gl);

    __half2 h01 = __floats2half2_rn(v.x, v.y);
    __half2 h23 = __floats2half2_rn(v.z, v.w);
    uint2 hp;
    hp.x = *reinterpret_cast<uint32_t*>(&h01);
    hp.y = *reinterpret_cast<uint32_t*>(&h23);
    reinterpret_cast<uint2*>(g_xh)[(size_t)node * 16 + gl] = hp;

    uint2 p0 = split2(v.x, v.y);
    uint2 p1 = split2(v.z, v.w);
    unsigned char* fr = g_feat + (size_t)node * 512;
    *reinterpret_cast<uint2*>(fr + 128 + gl * 8) = make_uint2(p0.x, p1.x);
    *reinterpret_cast<uint2*>(fr + 384 + gl * 8) = make_uint2(p0.y, p1.y);
}

// ======================= K1: gather =======================
// 8-lane group per node; batch of 4 edges accumulated in half2 (HADD2),
// converted to f32 once per batch.
__global__ __launch_bounds__(256)
void gather_kernel(const int* __restrict__ row,
                   const int* __restrict__ colptr,
                   int N)
{
    const int g  = (blockIdx.x * 256 + threadIdx.x) >> 3;
    const int gl = threadIdx.x & 7;
    if (g >= N) return;

    const uint4* xh4 = reinterpret_cast<const uint4*>(g_xh);

    const int e0 = __ldg(colptr + g);
    const int e1 = __ldg(colptr + g + 1);

    float acc[8];
    #pragma unroll
    for (int i = 0; i < 8; i++) acc[i] = 0.f;

    int e = e0;
    if (e + 4 <= e1) {
        int sa0 = __ldg(row + e), sa1 = __ldg(row + e + 1);
        int sa2 = __ldg(row + e + 2), sa3 = __ldg(row + e + 3);
        e += 4;
        while (true) {
            bool more = (e + 4 <= e1);
            int sb0 = 0, sb1 = 0, sb2 = 0, sb3 = 0;
            if (more) {
                sb0 = __ldg(row + e);     sb1 = __ldg(row + e + 1);
                sb2 = __ldg(row + e + 2); sb3 = __ldg(row + e + 3);
            }
            uint4 v0 = __ldg(xh4 + (size_t)sa0 * 8 + gl);
            uint4 v1 = __ldg(xh4 + (size_t)sa1 * 8 + gl);
            uint4 v2 = __ldg(xh4 + (size_t)sa2 * 8 + gl);
            uint4 v3 = __ldg(xh4 + (size_t)sa3 * 8 + gl);
            // batch-accumulate in half2 (fma pipe), convert once
            __half2 s0 = __hadd2(__hadd2(u2h(v0.x), u2h(v1.x)),
                                 __hadd2(u2h(v2.x), u2h(v3.x)));
            __half2 s1 = __hadd2(__hadd2(u2h(v0.y), u2h(v1.y)),
                                 __hadd2(u2h(v2.y), u2h(v3.y)));
            __half2 s2 = __hadd2(__hadd2(u2h(v0.z), u2h(v1.z)),
                                 __hadd2(u2h(v2.z), u2h(v3.z)));
            __half2 s3 = __hadd2(__hadd2(u2h(v0.w), u2h(v1.w)),
                                 __hadd2(u2h(v2.w), u2h(v3.w)));
            float2 f;
            f = __half22float2(s0); acc[0] += f.x; acc[1] += f.y;
            f = __half22float2(s1); acc[2] += f.x; acc[3] += f.y;
            f = __half22float2(s2); acc[4] += f.x; acc[5] += f.y;
            f = __half22float2(s3); acc[6] += f.x; acc[7] += f.y;
            if (!more) break;
            sa0 = sb0; sa1 = sb1; sa2 = sb2; sa3 = sb3;
            e += 4;
        }
    }
    for (; e < e1; e++) {
        int s = __ldg(row + e);
        uint4 v = __ldg(xh4 + (size_t)s * 8 + gl);
        float2 f;
        f = __half22float2(u2h(v.x)); acc[0] += f.x; acc[1] += f.y;
        f = __half22float2(u2h(v.y)); acc[2] += f.x; acc[3] += f.y;
        f = __half22float2(u2h(v.z)); acc[4] += f.x; acc[5] += f.y;
        f = __half22float2(u2h(v.w)); acc[6] += f.x; acc[7] += f.y;
    }

    const int deg = e1 - e0;
    const float inv = 1.f / (float)(deg > 0 ? deg : 1);
    #pragma unroll
    for (int i = 0; i < 8; i++) acc[i] *= inv;

    uint2 p0 = split2(acc[0], acc[1]);
    uint2 p1 = split2(acc[2], acc[3]);
    uint2 p2 = split2(acc[4], acc[5]);
    uint2 p3 = split2(acc[6], acc[7]);
    unsigned char* fr = g_feat + (size_t)g * 512;
    *reinterpret_cast<uint4*>(fr + gl * 16)       = make_uint4(p0.x, p1.x, p2.x, p3.x);
    *reinterpret_cast<uint4*>(fr + 256 + gl * 16) = make_uint4(p0.y, p1.y, p2.y, p3.y);
}

// ======================= K2: HMMA GEMM =======================
#define GB   128
#define ROWB 272
#define SM_AHI 0
#define SM_ALO 34816
#define SM_WHI 69632
#define SM_WLO 87040
#define SM_TOT 104448

extern __shared__ char g_sm[];

__global__ __launch_bounds__(256, 2)
void gemm_mma_kernel(const float* __restrict__ b,
                     float*       __restrict__ out,
                     int N)
{
    const uint32_t sb = smem_u32(g_sm);
    const int tid  = threadIdx.x;
    const int wid  = tid >> 5;
    const int lane = tid & 31;
    const int base = blockIdx.x * GB;

    // thread roles for A staging: row m, half (hi/lo)
    const int am    = tid & 127;
    const int ahalf = tid >> 7;
    const unsigned char* asrc = g_feat + (size_t)(base + am) * 512 + ahalf * 256;
    const uint32_t adst = sb + (ahalf ? SM_ALO : SM_AHI) + am * ROWB;

    // ---- stage k-half 0 (bytes [0,128) of each row) -> group 0 ----
    #pragma unroll
    for (int i = 0; i < 8; i++)
        cp16(adst + i * 16, asrc + i * 16);
    #pragma unroll
    for (int j = 0; j < 4; j++) {                 // W: 1024 chunks of khalf0
        const int c = tid + 256 * j;              // 0..1023
        const int o = c >> 4;
        const int q = c & 15;                     // 0..7 hi-k0, 8..15 lo-k0
        const int hl = q >> 3;                    // 0 hi, 1 lo
        const int qi = q & 7;
        const unsigned char* src = g_wcvt + (size_t)o * 512 + hl * 256 + qi * 16;
        const uint32_t dst = sb + (hl ? SM_WLO : SM_WHI) + o * ROWB + qi * 16;
        cp16(dst, src);
    }
    asm volatile("cp.async.commit_group;" ::: "memory");

    // ---- stage k-half 1 (bytes [128,256) of each row) -> group 1 ----
    #pragma unroll
    for (int i = 8; i < 16; i++)
        cp16(adst + i * 16, asrc + i * 16);
    #pragma unroll
    for (int j = 0; j < 4; j++) {
        const int c = tid + 256 * j;
        const int o = c >> 4;
        const int q = c & 15;
        const int hl = q >> 3;
        const int qi = (q & 7) + 8;
        const unsigned char* src = g_wcvt + (size_t)o * 512 + hl * 256 + qi * 16;
        const uint32_t dst = sb + (hl ? SM_WLO : SM_WHI) + o * ROWB + qi * 16;
        cp16(dst, src);
    }
    asm volatile("cp.async.commit_group;" ::: "memory");

    // warp grid: 4 m-warps x 2 n-warps; warp tile 32 nodes x 32 outs
    const int wm = wid >> 1;
    const int wn = wid & 1;

    const uint32_t a_base = sb + SM_AHI
        + (uint32_t)(wm * 32 + (lane & 15)) * ROWB + (uint32_t)(lane >> 4) * 16;
    const int brow = wn * 32 + ((lane >> 4) << 3) + (lane & 7);
    const uint32_t b_base = sb + SM_WHI
        + (uint32_t)brow * ROWB + (uint32_t)((lane >> 3) & 1) * 16;

    float acc[2][4][4];
    #pragma unroll
    for (int i = 0; i < 2; i++)
        #pragma unroll
        for (int j = 0; j < 4; j++)
            #pragma unroll
            for (int q = 0; q < 4; q++) acc[i][j][q] = 0.f;

    // ---- stage 0 ready: compute ks 0..3 ----
    asm volatile("cp.async.wait_group 1;" ::: "memory");
    __syncthreads();

    #pragma unroll
    for (int ks = 0; ks < 8; ks++) {
        if (ks == 4) {
            asm volatile("cp.async.wait_group 0;" ::: "memory");
            __syncthreads();
        }
        const uint32_t ao = a_base + ks * 32;
        const uint32_t bo = b_base + ks * 32;
        uint4 ah0, ah1, al0, al1, bh0, bh1, bl0, bl1;
        ldm_x4(ah0, ao);
        ldm_x4(ah1, ao + 16 * ROWB);
        ldm_x4(al0, ao + (SM_ALO - SM_AHI));
        ldm_x4(al1, ao + (SM_ALO - SM_AHI) + 16 * ROWB);
        ldm_x4(bh0, bo);
        ldm_x4(bh1, bo + 16 * ROWB);
        ldm_x4(bl0, bo + (SM_WLO - SM_WHI));
        ldm_x4(bl1, bo + (SM_WLO - SM_WHI) + 16 * ROWB);

        mma16816(acc[0][0], ah0, bh0.x, bh0.y);
        mma16816(acc[0][1], ah0, bh0.z, bh0.w);
        mma16816(acc[0][2], ah0, bh1.x, bh1.y);
        mma16816(acc[0][3], ah0, bh1.z, bh1.w);
        mma16816(acc[1][0], ah1, bh0.x, bh0.y);
        mma16816(acc[1][1], ah1, bh0.z, bh0.w);
        mma16816(acc[1][2], ah1, bh1.x, bh1.y);
        mma16816(acc[1][3], ah1, bh1.z, bh1.w);

        mma16816(acc[0][0], ah0, bl0.x, bl0.y);
        mma16816(acc[0][1], ah0, bl0.z, bl0.w);
        mma16816(acc[0][2], ah0, bl1.x, bl1.y);
        mma16816(acc[0][3], ah0, bl1.z, bl1.w);
        mma16816(acc[1][0], ah1, bl0.x, bl0.y);
        mma16816(acc[1][1], ah1, bl0.z, bl0.w);
        mma16816(acc[1][2], ah1, bl1.x, bl1.y);
        mma16816(acc[1][3], ah1, bl1.z, bl1.w);

        mma16816(acc[0][0], al0, bh0.x, bh0.y);
        mma16816(acc[0][1], al0, bh0.z, bh0.w);
        mma16816(acc[0][2], al0, bh1.x, bh1.y);
        mma16816(acc[0][3], al0, bh1.z, bh1.w);
        mma16816(acc[1][0], al1, bh0.x, bh0.y);
        mma16816(acc[1][1], al1, bh0.z, bh0.w);
        mma16816(acc[1][2], al1, bh1.x, bh1.y);
        mma16816(acc[1][3], al1, bh1.z, bh1.w);
    }

    // ---- epilogue ----
    const int g   = lane >> 2;
    const int tig = lane & 3;
    float2 bb[4];
    #pragma unroll
    for (int ns = 0; ns < 4; ns++) {
        int col = wn * 32 + ns * 8 + 2 * tig;
        bb[ns] = make_float2(__ldg(b + col), __ldg(b + col + 1));
    }
    #pragma unroll
    for (int ms = 0; ms < 2; ms++) {
        const int node0 = base + wm * 32 + ms * 16 + g;
        const int node1 = node0 + 8;
        #pragma unroll
        for (int ns = 0; ns < 4; ns++) {
            const int col = wn * 32 + ns * 8 + 2 * tig;
            if (node0 < N) {
                *reinterpret_cast<float2*>(out + (size_t)node0 * D_OUT + col) =
                    make_float2(acc[ms][ns][0] + bb[ns].x, acc[ms][ns][1] + bb[ns].y);
            }
            if (node1 < N) {
                *reinterpret_cast<float2*>(out + (size_t)node1 * D_OUT + col) =
                    make_float2(acc[ms][ns][2] + bb[ns].x, acc[ms][ns][3] + bb[ns].y);
            }
        }
    }
}

// ======================= launch =======================
extern "C" void kernel_launch(void* const* d_in, const int* in_sizes, int n_in,
                              void* d_out, int out_size)
{
    const float* x      = (const float*)d_in[0];
    const int*   row    = (const int*)  d_in[1];
    const int*   colptr = (const int*)  d_in[2];
    const float* W      = (const float*)d_in[3];
    const float* b      = (const float*)d_in[4];
    float*       out    = (float*)d_out;

    const int N = in_sizes[2] - 1;   // 100000

    cudaFuncSetAttribute(gemm_mma_kernel,
                         cudaFuncAttributeMaxDynamicSharedMemorySize, SM_TOT);

    convert_kernel<<<XBLOCKS + 8, 256>>>(
        reinterpret_cast<const float4*>(x),
        reinterpret_cast<const float4*>(W), N);

    gather_kernel<<<(N * 8 + 255) / 256, 256>>>(row, colptr, N);

    int gemm_grid = (N + GB - 1) / GB;
    gemm_mma_kernel<<<gemm_grid, 256, SM_TOT>>>(b, out, N);
}